// round 8
// baseline (speedup 1.0000x reference)
#include <cuda_runtime.h>
#include <math.h>

#define B 4
#define N 8192
#define M 8192
#define EPS 1e-8f
#define TSR 128   // source rows per tile (CTA)
#define TSC 128   // target cols per tile
#define NT  8     // col tiles swept per CTA
#define CGROUPS (M / (TSC * NT))   // 8 col groups
#define RTILES (N / TSR)           // 64

typedef unsigned long long u64;

// Per-tile partial minima (squared distances). Plain stores — no init, no atomics.
__device__ float g_rowpart[B * CGROUPS * N];   // [b][colGroup][row]
__device__ float g_colpart[B * RTILES * M];    // [b][rowTile][col]
__device__ float g_bsum[256];

// ---------------- packed f32x2 helpers ----------------
__device__ __forceinline__ u64 pk2(float a, float b) {
    u64 r;
    asm("mov.b64 %0, {%1, %2};" : "=l"(r) : "f"(a), "f"(b));
    return r;
}
__device__ __forceinline__ u64 add2(u64 a, u64 b) {
    u64 r;
    asm("add.rn.f32x2 %0, %1, %2;" : "=l"(r) : "l"(a), "l"(b));
    return r;
}
__device__ __forceinline__ u64 fma2(u64 a, u64 b, u64 c) {
    u64 r;
    asm("fma.rn.f32x2 %0, %1, %2, %3;" : "=l"(r) : "l"(a), "l"(b), "l"(c));
    return r;
}
__device__ __forceinline__ float2 u2f(u64 v) {
    float2 f;
    asm("mov.b64 {%0, %1}, %2;" : "=f"(f.x), "=f"(f.y) : "l"(v));
    return f;
}

// ---------------- fused sweep kernel ----------------
// CTA: 128 source rows x (8 tiles of 128 target cols). 256 threads (16x16);
// per tile each thread covers 8 rows x 8 cols (4 f32x2 col-pairs).
// Software-pipelined min/fma blocks; small register footprint so ptxas can
// hoist the per-row LDS across iterations. 3 CTAs/SM.
__global__ __launch_bounds__(256, 3) void tile_kernel(const float* __restrict__ source,
                                                      const float* __restrict__ target) {
    __shared__ __align__(16) u64 s_px[TSR], s_py[TSR], s_pz[TSR], s_pn[TSR];
    __shared__ __align__(16) float t2x[TSC], t2y[TSC], t2z[TSC], t_n[TSC];  // -2*t, ||t||^2
    __shared__ float red[TSR * 17];

    const int tid = threadIdx.x;
    const int b   = blockIdx.z;
    const int row0 = blockIdx.y * TSR;
    const int g    = blockIdx.x;          // col group
    const int colg0 = g * (TSC * NT);

    // Stage source tile: duplicated coords + norm (once per CTA)
    if (tid < TSR) {
        const float* sp = source + ((long)b * N + row0 + tid) * 3;
        float vx = sp[0], vy = sp[1], vz = sp[2];
        s_px[tid] = pk2(vx, vx);
        s_py[tid] = pk2(vy, vy);
        s_pz[tid] = pk2(vz, vz);
        float n = vx * vx + vy * vy + vz * vz;
        s_pn[tid] = pk2(n, n);
    }
    // Stage first target tile
    if (tid < TSC) {
        const float* tp = target + ((long)b * M + colg0 + tid) * 3;
        float vx = tp[0], vy = tp[1], vz = tp[2];
        t2x[tid] = -2.0f * vx; t2y[tid] = -2.0f * vy; t2z[tid] = -2.0f * vz;
        t_n[tid] = vx * vx + vy * vy + vz * vz;
    }
    __syncthreads();

    const int txi = tid & 15;
    const int tyi = tid >> 4;
    const int r0 = tyi * 8;   // local rows r0..r0+7
    const int c0 = txi * 8;   // local cols c0..c0+7 (4 pairs)

    const float BIGF = 3.4e38f;
    float rmin[8];
#pragma unroll
    for (int i = 0; i < 8; i++) rmin[i] = BIGF;

    float nx = 0.f, ny = 0.f, nz = 0.f;  // next-tile target prefetch regs

    for (int ct = 0; ct < NT; ct++) {
        // Prefetch next tile's target points (LDG hidden behind compute)
        if (ct + 1 < NT && tid < TSC) {
            const float* tp = target + ((long)b * M + colg0 + (ct + 1) * TSC + tid) * 3;
            nx = tp[0]; ny = tp[1]; nz = tp[2];
        }

        // Per-thread column constants: 4 pairs x {t2x, t2y, t2z, tn}
        u64 ctx[4], cty[4], ctz[4], ctn[4];
#pragma unroll
        for (int j = 0; j < 4; j++) {
            float2 vx = *reinterpret_cast<const float2*>(&t2x[c0 + 2 * j]);
            float2 vy = *reinterpret_cast<const float2*>(&t2y[c0 + 2 * j]);
            float2 vz = *reinterpret_cast<const float2*>(&t2z[c0 + 2 * j]);
            float2 vn = *reinterpret_cast<const float2*>(&t_n[c0 + 2 * j]);
            ctx[j] = pk2(vx.x, vx.y);
            cty[j] = pk2(vy.x, vy.y);
            ctz[j] = pk2(vz.x, vz.y);
            ctn[j] = pk2(vn.x, vn.y);
        }

        float cl[8];
#pragma unroll
        for (int k = 0; k < 8; k++) cl[k] = BIGF;

        // ---- software-pipelined row loop ----
        u64 qp[4];  // distances for previous row (pending mins)
        {
            u64 sxd = s_px[r0], syd = s_py[r0], szd = s_pz[r0], snd = s_pn[r0];
#pragma unroll
            for (int j = 0; j < 4; j++) {
                u64 q = fma2(sxd, ctx[j], add2(ctn[j], snd));
                q = fma2(syd, cty[j], q);
                qp[j] = fma2(szd, ctz[j], q);
            }
        }
#pragma unroll
        for (int i = 1; i < 8; i++) {
            // fma block for row i (independent of min block below)
            u64 sxd = s_px[r0 + i], syd = s_py[r0 + i], szd = s_pz[r0 + i], snd = s_pn[r0 + i];
            u64 qc[4];
#pragma unroll
            for (int j = 0; j < 4; j++) {
                u64 q = fma2(sxd, ctx[j], add2(ctn[j], snd));
                q = fma2(syd, cty[j], q);
                qc[j] = fma2(szd, ctz[j], q);
            }
            // min block for row i-1 (operands a full iteration old)
            {
                float2 q0 = u2f(qp[0]), q1 = u2f(qp[1]), q2 = u2f(qp[2]), q3 = u2f(qp[3]);
                cl[0] = fminf(cl[0], q0.x); cl[1] = fminf(cl[1], q0.y);
                cl[2] = fminf(cl[2], q1.x); cl[3] = fminf(cl[3], q1.y);
                cl[4] = fminf(cl[4], q2.x); cl[5] = fminf(cl[5], q2.y);
                cl[6] = fminf(cl[6], q3.x); cl[7] = fminf(cl[7], q3.y);
                float a = fminf(fminf(q0.x, q0.y), fminf(q1.x, q1.y));
                float c = fminf(fminf(q2.x, q2.y), fminf(q3.x, q3.y));
                rmin[i - 1] = fminf(rmin[i - 1], fminf(a, c));
            }
#pragma unroll
            for (int j = 0; j < 4; j++) qp[j] = qc[j];
        }
        // drain: mins for last row
        {
            float2 q0 = u2f(qp[0]), q1 = u2f(qp[1]), q2 = u2f(qp[2]), q3 = u2f(qp[3]);
            cl[0] = fminf(cl[0], q0.x); cl[1] = fminf(cl[1], q0.y);
            cl[2] = fminf(cl[2], q1.x); cl[3] = fminf(cl[3], q1.y);
            cl[4] = fminf(cl[4], q2.x); cl[5] = fminf(cl[5], q2.y);
            cl[6] = fminf(cl[6], q3.x); cl[7] = fminf(cl[7], q3.y);
            float a = fminf(fminf(q0.x, q0.y), fminf(q1.x, q1.y));
            float c = fminf(fminf(q2.x, q2.y), fminf(q3.x, q3.y));
            rmin[7] = fminf(rmin[7], fminf(a, c));
        }

        // ---- col-min reduction for this tile (across tyi) ----
#pragma unroll
        for (int k = 0; k < 8; k++) red[(c0 + k) * 17 + tyi] = cl[k];
        __syncthreads();
        if (tid < TSC) {
            float m = red[tid * 17];
#pragma unroll
            for (int k = 1; k < 16; k++) m = fminf(m, red[tid * 17 + k]);
            g_colpart[((long)b * RTILES + blockIdx.y) * M + colg0 + ct * TSC + tid] = m;
        }
        __syncthreads();

        // Commit prefetched target tile to smem for next iteration
        if (ct + 1 < NT) {
            if (tid < TSC) {
                t2x[tid] = -2.0f * nx; t2y[tid] = -2.0f * ny; t2z[tid] = -2.0f * nz;
                t_n[tid] = nx * nx + ny * ny + nz * nz;
            }
            __syncthreads();
        }
    }

    // ---- row-min reduction (across txi), once per CTA ----
#pragma unroll
    for (int i = 0; i < 8; i++) red[(r0 + i) * 17 + txi] = rmin[i];
    __syncthreads();
    if (tid < TSR) {
        float m = red[tid * 17];
#pragma unroll
        for (int k = 1; k < 16; k++) m = fminf(m, red[tid * 17 + k]);
        g_rowpart[((long)b * CGROUPS + g) * N + row0 + tid] = m;
    }
}

// ---------------- finalize pass 1: reduce partials, block sums ----------------
__global__ void finalize1_kernel(const float* __restrict__ weights) {
    __shared__ float sred[256];
    int tid = blockIdx.x * blockDim.x + threadIdx.x;
    float v;
    if (tid < B * N) {
        int b = tid >> 13, row = tid & 8191;
        const float* p = &g_rowpart[((long)b * CGROUPS) * N + row];
        float m = p[0];
#pragma unroll
        for (int ct = 1; ct < CGROUPS; ct++) m = fminf(m, p[(long)ct * N]);
        v = sqrtf(m + EPS) * weights[tid] * (1.0f / (B * N));
    } else {
        int t = tid - B * N;
        int b = t >> 13, col = t & 8191;
        const float* p = &g_colpart[((long)b * RTILES) * M + col];
        float m = p[0];
#pragma unroll 8
        for (int rt = 1; rt < RTILES; rt++) m = fminf(m, p[(long)rt * M]);
        v = sqrtf(m + EPS) * (1.0f / (B * M));
    }
    sred[threadIdx.x] = v;
    __syncthreads();
    for (int s = 128; s > 0; s >>= 1) {
        if (threadIdx.x < s) sred[threadIdx.x] += sred[threadIdx.x + s];
        __syncthreads();
    }
    if (threadIdx.x == 0) g_bsum[blockIdx.x] = sred[0];
}

// ---------------- finalize pass 2: single block, plain store ----------------
__global__ void finalize2_kernel(float* __restrict__ out) {
    __shared__ float sred[256];
    sred[threadIdx.x] = g_bsum[threadIdx.x];
    __syncthreads();
    for (int s = 128; s > 0; s >>= 1) {
        if (threadIdx.x < s) sred[threadIdx.x] += sred[threadIdx.x + s];
        __syncthreads();
    }
    if (threadIdx.x == 0) out[0] = sred[0];
}

extern "C" void kernel_launch(void* const* d_in, const int* in_sizes, int n_in,
                              void* d_out, int out_size) {
    const float* source  = (const float*)d_in[0];
    const float* target  = (const float*)d_in[1];
    const float* weights = (const float*)d_in[2];
    float* out = (float*)d_out;

    dim3 grid(CGROUPS, RTILES, B);
    tile_kernel<<<grid, 256>>>(source, target);

    finalize1_kernel<<<(B * N + B * M) / 256, 256>>>(weights);
    finalize2_kernel<<<1, 256>>>(out);
}

// round 9
// speedup vs baseline: 1.1926x; 1.1926x over previous
#include <cuda_runtime.h>
#include <math.h>

#define B 4
#define N 8192
#define M 8192
#define EPS 1e-8f
#define TSR 256   // source rows per CTA
#define TSC 128   // target cols per tile
#define NT  8     // col tiles swept per CTA
#define CGROUPS (M / (TSC * NT))   // 8 col groups
#define RTILES (N / TSR)           // 32

typedef unsigned long long u64;

__device__ float g_rowpart[B * CGROUPS * N];   // [b][colGroup][row]
__device__ float g_colpart[B * RTILES * M];    // [b][rowTile][col]
__device__ float g_bsum[256];

// ---------------- packed f32x2 helpers ----------------
__device__ __forceinline__ u64 pk2(float a, float b) {
    u64 r;
    asm("mov.b64 %0, {%1, %2};" : "=l"(r) : "f"(a), "f"(b));
    return r;
}
__device__ __forceinline__ u64 add2(u64 a, u64 b) {
    u64 r;
    asm("add.rn.f32x2 %0, %1, %2;" : "=l"(r) : "l"(a), "l"(b));
    return r;
}
__device__ __forceinline__ u64 fma2(u64 a, u64 b, u64 c) {
    u64 r;
    asm("fma.rn.f32x2 %0, %1, %2, %3;" : "=l"(r) : "l"(a), "l"(b), "l"(c));
    return r;
}
__device__ __forceinline__ float2 u2f(u64 v) {
    float2 f;
    asm("mov.b64 {%0, %1}, %2;" : "=f"(f.x), "=f"(f.y) : "l"(v));
    return f;
}

// ---------------- fused sweep kernel ----------------
// CTA: 256 source rows x (8 tiles of 128 target cols). 256 threads (16 tyi x 16 txi).
// INVERTED packing: each f32x2 pair holds TWO SOURCE ROWS; target is duplicated.
// Each thread's 16 rows (8 pairs x 4 coords = 32 u64) live in registers for the
// whole CTA. Per tile only 4 LDS.64 per column are needed.
__global__ __launch_bounds__(256, 2) void tile_kernel(const float* __restrict__ source,
                                                      const float* __restrict__ target) {
    __shared__ __align__(16) float s_x[TSR], s_y[TSR], s_z[TSR], s_n[TSR];   // scalar source
    __shared__ __align__(16) u64 td_x[TSC], td_y[TSC], td_z[TSC], td_n[TSC]; // dup (-2t), (nt)
    __shared__ float red[TSR * 17];

    const int tid = threadIdx.x;
    const int b   = blockIdx.z;
    const int row0 = blockIdx.y * TSR;
    const int g    = blockIdx.x;
    const int colg0 = g * (TSC * NT);

    // Stage source (scalar): one row per thread
    {
        const float* sp = source + ((long)b * N + row0 + tid) * 3;
        float vx = sp[0], vy = sp[1], vz = sp[2];
        s_x[tid] = vx; s_y[tid] = vy; s_z[tid] = vz;
        s_n[tid] = vx * vx + vy * vy + vz * vz;
    }
    // Stage first target tile: duplicated pairs
    if (tid < TSC) {
        const float* tp = target + ((long)b * M + colg0 + tid) * 3;
        float vx = tp[0], vy = tp[1], vz = tp[2];
        td_x[tid] = pk2(-2.0f * vx, -2.0f * vx);
        td_y[tid] = pk2(-2.0f * vy, -2.0f * vy);
        td_z[tid] = pk2(-2.0f * vz, -2.0f * vz);
        float n = vx * vx + vy * vy + vz * vz;
        td_n[tid] = pk2(n, n);
    }
    __syncthreads();

    const int txi = tid & 15;
    const int tyi = tid >> 4;
    const int r0 = tyi * 16;  // this thread's 16 rows
    const int c0 = txi * 8;   // this thread's 8 cols per tile

    // Load source row-pairs into registers ONCE (LDS.64 of adjacent scalars)
    u64 px[8], py[8], pz[8], pn[8];
#pragma unroll
    for (int a = 0; a < 8; a++) {
        px[a] = *reinterpret_cast<const u64*>(&s_x[r0 + 2 * a]);
        py[a] = *reinterpret_cast<const u64*>(&s_y[r0 + 2 * a]);
        pz[a] = *reinterpret_cast<const u64*>(&s_z[r0 + 2 * a]);
        pn[a] = *reinterpret_cast<const u64*>(&s_n[r0 + 2 * a]);
    }

    const float BIGF = 3.4e38f;
    float rmin[16];
#pragma unroll
    for (int i = 0; i < 16; i++) rmin[i] = BIGF;

    float nx = 0.f, ny = 0.f, nz = 0.f;  // next-tile prefetch

    for (int ct = 0; ct < NT; ct++) {
        if (ct + 1 < NT && tid < TSC) {
            const float* tp = target + ((long)b * M + colg0 + (ct + 1) * TSC + tid) * 3;
            nx = tp[0]; ny = tp[1]; nz = tp[2];
        }

#pragma unroll
        for (int c = 0; c < 8; c++) {
            const int col = c0 + c;
            u64 tx = td_x[col], ty = td_y[col], tz = td_z[col], tn = td_n[col];
            float cc0 = BIGF, cc1 = BIGF;  // two independent col-min chains
#pragma unroll
            for (int a = 0; a < 8; a++) {
                u64 q = fma2(px[a], tx, add2(pn[a], tn));
                q = fma2(py[a], ty, q);
                q = fma2(pz[a], tz, q);       // q = (d^2 row 2a, d^2 row 2a+1)
                float2 f = u2f(q);
                rmin[2 * a]     = fminf(rmin[2 * a], f.x);
                rmin[2 * a + 1] = fminf(rmin[2 * a + 1], f.y);
                cc0 = fminf(cc0, f.x);
                cc1 = fminf(cc1, f.y);
            }
            red[col * 17 + tyi] = fminf(cc0, cc1);
        }
        __syncthreads();
        // col-min reduction across tyi (16 values per col)
        if (tid < TSC) {
            float m = red[tid * 17];
#pragma unroll
            for (int k = 1; k < 16; k++) m = fminf(m, red[tid * 17 + k]);
            g_colpart[((long)b * RTILES + blockIdx.y) * M + colg0 + ct * TSC + tid] = m;
        }
        __syncthreads();

        // Commit prefetched target tile
        if (ct + 1 < NT) {
            if (tid < TSC) {
                td_x[tid] = pk2(-2.0f * nx, -2.0f * nx);
                td_y[tid] = pk2(-2.0f * ny, -2.0f * ny);
                td_z[tid] = pk2(-2.0f * nz, -2.0f * nz);
                float n = nx * nx + ny * ny + nz * nz;
                td_n[tid] = pk2(n, n);
            }
            __syncthreads();
        }
    }

    // ---- row-min reduction (across txi), once per CTA ----
#pragma unroll
    for (int i = 0; i < 16; i++) red[(r0 + i) * 17 + txi] = rmin[i];
    __syncthreads();
    {
        float m = red[tid * 17];
#pragma unroll
        for (int k = 1; k < 16; k++) m = fminf(m, red[tid * 17 + k]);
        g_rowpart[((long)b * CGROUPS + g) * N + row0 + tid] = m;
    }
}

// ---------------- finalize pass 1: reduce partials, block sums ----------------
__global__ void finalize1_kernel(const float* __restrict__ weights) {
    __shared__ float sred[256];
    int tid = blockIdx.x * blockDim.x + threadIdx.x;
    float v;
    if (tid < B * N) {
        int b = tid >> 13, row = tid & 8191;
        const float* p = &g_rowpart[((long)b * CGROUPS) * N + row];
        float m = p[0];
#pragma unroll
        for (int ct = 1; ct < CGROUPS; ct++) m = fminf(m, p[(long)ct * N]);
        v = sqrtf(m + EPS) * weights[tid] * (1.0f / (B * N));
    } else {
        int t = tid - B * N;
        int b = t >> 13, col = t & 8191;
        const float* p = &g_colpart[((long)b * RTILES) * M + col];
        float m = p[0];
#pragma unroll 8
        for (int rt = 1; rt < RTILES; rt++) m = fminf(m, p[(long)rt * M]);
        v = sqrtf(m + EPS) * (1.0f / (B * M));
    }
    sred[threadIdx.x] = v;
    __syncthreads();
    for (int s = 128; s > 0; s >>= 1) {
        if (threadIdx.x < s) sred[threadIdx.x] += sred[threadIdx.x + s];
        __syncthreads();
    }
    if (threadIdx.x == 0) g_bsum[blockIdx.x] = sred[0];
}

// ---------------- finalize pass 2: single block, plain store ----------------
__global__ void finalize2_kernel(float* __restrict__ out) {
    __shared__ float sred[256];
    sred[threadIdx.x] = g_bsum[threadIdx.x];
    __syncthreads();
    for (int s = 128; s > 0; s >>= 1) {
        if (threadIdx.x < s) sred[threadIdx.x] += sred[threadIdx.x + s];
        __syncthreads();
    }
    if (threadIdx.x == 0) out[0] = sred[0];
}

extern "C" void kernel_launch(void* const* d_in, const int* in_sizes, int n_in,
                              void* d_out, int out_size) {
    const float* source  = (const float*)d_in[0];
    const float* target  = (const float*)d_in[1];
    const float* weights = (const float*)d_in[2];
    float* out = (float*)d_out;

    dim3 grid(CGROUPS, RTILES, B);
    tile_kernel<<<grid, 256>>>(source, target);

    finalize1_kernel<<<(B * N + B * M) / 256, 256>>>(weights);
    finalize2_kernel<<<1, 256>>>(out);
}

// round 10
// speedup vs baseline: 1.4642x; 1.2277x over previous
#include <cuda_runtime.h>
#include <math.h>

#define B 4
#define N 8192
#define M 8192
#define EPS 1e-8f
#define TSR 256   // source rows per CTA
#define TSC 128   // target cols per tile
#define NT  8     // col tiles swept per CTA
#define CGROUPS (M / (TSC * NT))   // 8 col groups
#define RTILES (N / TSR)           // 32

typedef unsigned long long u64;

__device__ float g_rowpart[B * CGROUPS * N];   // [b][colGroup][row]
__device__ float g_colpart[B * RTILES * M];    // [b][rowTile][col]
__device__ float g_bsum[256];

// ---------------- packed f32x2 helpers ----------------
__device__ __forceinline__ u64 pk2(float a, float b) {
    u64 r;
    asm("mov.b64 %0, {%1, %2};" : "=l"(r) : "f"(a), "f"(b));
    return r;
}
__device__ __forceinline__ u64 add2(u64 a, u64 b) {
    u64 r;
    asm("add.rn.f32x2 %0, %1, %2;" : "=l"(r) : "l"(a), "l"(b));
    return r;
}
__device__ __forceinline__ u64 fma2(u64 a, u64 b, u64 c) {
    u64 r;
    asm("fma.rn.f32x2 %0, %1, %2, %3;" : "=l"(r) : "l"(a), "l"(b), "l"(c));
    return r;
}
__device__ __forceinline__ float2 u2f(u64 v) {
    float2 f;
    asm("mov.b64 {%0, %1}, %2;" : "=f"(f.x), "=f"(f.y) : "l"(v));
    return f;
}

// ---------------- fused sweep kernel ----------------
// CTA: 256 source rows x (8 tiles of 128 target cols). 256 threads (16 tyi x 16 txi).
// Vertical packing: each f32x2 pair = TWO SOURCE ROWS; target duplicated.
// Source (8 pairs x 4 coords = 32 u64) register-resident for the whole CTA.
// Column mapping col = c*16 + txi -> per-column LDS.64 are UNIT-STRIDE across
// lanes (conflict-free, 2x tyi broadcast).
__global__ __launch_bounds__(256, 2) void tile_kernel(const float* __restrict__ source,
                                                      const float* __restrict__ target) {
    __shared__ __align__(16) float s_x[TSR], s_y[TSR], s_z[TSR], s_n[TSR];   // scalar source
    __shared__ __align__(16) u64 td_x[TSC], td_y[TSC], td_z[TSC], td_n[TSC]; // dup (-2t), (nt)
    __shared__ float red[TSR * 17];

    const int tid = threadIdx.x;
    const int b   = blockIdx.z;
    const int row0 = blockIdx.y * TSR;
    const int g    = blockIdx.x;
    const int colg0 = g * (TSC * NT);

    // Stage source (scalar): one row per thread
    {
        const float* sp = source + ((long)b * N + row0 + tid) * 3;
        float vx = sp[0], vy = sp[1], vz = sp[2];
        s_x[tid] = vx; s_y[tid] = vy; s_z[tid] = vz;
        s_n[tid] = vx * vx + vy * vy + vz * vz;
    }
    // Stage first target tile: duplicated pairs
    if (tid < TSC) {
        const float* tp = target + ((long)b * M + colg0 + tid) * 3;
        float vx = tp[0], vy = tp[1], vz = tp[2];
        td_x[tid] = pk2(-2.0f * vx, -2.0f * vx);
        td_y[tid] = pk2(-2.0f * vy, -2.0f * vy);
        td_z[tid] = pk2(-2.0f * vz, -2.0f * vz);
        float n = vx * vx + vy * vy + vz * vz;
        td_n[tid] = pk2(n, n);
    }
    __syncthreads();

    const int txi = tid & 15;
    const int tyi = tid >> 4;
    const int r0 = tyi * 16;  // this thread's 16 rows

    // Load source row-pairs into registers ONCE (LDS.64 of adjacent scalars)
    u64 px[8], py[8], pz[8], pn[8];
#pragma unroll
    for (int a = 0; a < 8; a++) {
        px[a] = *reinterpret_cast<const u64*>(&s_x[r0 + 2 * a]);
        py[a] = *reinterpret_cast<const u64*>(&s_y[r0 + 2 * a]);
        pz[a] = *reinterpret_cast<const u64*>(&s_z[r0 + 2 * a]);
        pn[a] = *reinterpret_cast<const u64*>(&s_n[r0 + 2 * a]);
    }

    const float BIGF = 3.4e38f;
    float rmin[16];
#pragma unroll
    for (int i = 0; i < 16; i++) rmin[i] = BIGF;

    float nx = 0.f, ny = 0.f, nz = 0.f;  // next-tile prefetch

    for (int ct = 0; ct < NT; ct++) {
        if (ct + 1 < NT && tid < TSC) {
            const float* tp = target + ((long)b * M + colg0 + (ct + 1) * TSC + tid) * 3;
            nx = tp[0]; ny = tp[1]; nz = tp[2];
        }

#pragma unroll
        for (int c = 0; c < 8; c++) {
            const int col = c * 16 + txi;   // unit stride across lanes: conflict-free
            u64 tx = td_x[col], ty = td_y[col], tz = td_z[col], tn = td_n[col];
            float cc0 = BIGF, cc1 = BIGF;  // two independent col-min chains
#pragma unroll
            for (int a = 0; a < 8; a++) {
                u64 q = fma2(px[a], tx, add2(pn[a], tn));
                q = fma2(py[a], ty, q);
                q = fma2(pz[a], tz, q);       // q = (d^2 row 2a, d^2 row 2a+1)
                float2 f = u2f(q);
                rmin[2 * a]     = fminf(rmin[2 * a], f.x);
                rmin[2 * a + 1] = fminf(rmin[2 * a + 1], f.y);
                cc0 = fminf(cc0, f.x);
                cc1 = fminf(cc1, f.y);
            }
            red[col * 17 + tyi] = fminf(cc0, cc1);
        }
        __syncthreads();
        // col-min reduction across tyi (16 values per col)
        if (tid < TSC) {
            float m = red[tid * 17];
#pragma unroll
            for (int k = 1; k < 16; k++) m = fminf(m, red[tid * 17 + k]);
            g_colpart[((long)b * RTILES + blockIdx.y) * M + colg0 + ct * TSC + tid] = m;
        }
        __syncthreads();

        // Commit prefetched target tile
        if (ct + 1 < NT) {
            if (tid < TSC) {
                td_x[tid] = pk2(-2.0f * nx, -2.0f * nx);
                td_y[tid] = pk2(-2.0f * ny, -2.0f * ny);
                td_z[tid] = pk2(-2.0f * nz, -2.0f * nz);
                float n = nx * nx + ny * ny + nz * nz;
                td_n[tid] = pk2(n, n);
            }
            __syncthreads();
        }
    }

    // ---- row-min reduction (across txi), once per CTA ----
#pragma unroll
    for (int i = 0; i < 16; i++) red[(r0 + i) * 17 + txi] = rmin[i];
    __syncthreads();
    {
        float m = red[tid * 17];
#pragma unroll
        for (int k = 1; k < 16; k++) m = fminf(m, red[tid * 17 + k]);
        g_rowpart[((long)b * CGROUPS + g) * N + row0 + tid] = m;
    }
}

// ---------------- finalize pass 1: reduce partials, block sums ----------------
__global__ void finalize1_kernel(const float* __restrict__ weights) {
    __shared__ float sred[256];
    int tid = blockIdx.x * blockDim.x + threadIdx.x;
    float v;
    if (tid < B * N) {
        int b = tid >> 13, row = tid & 8191;
        const float* p = &g_rowpart[((long)b * CGROUPS) * N + row];
        float m = p[0];
#pragma unroll
        for (int ct = 1; ct < CGROUPS; ct++) m = fminf(m, p[(long)ct * N]);
        v = sqrtf(m + EPS) * weights[tid] * (1.0f / (B * N));
    } else {
        int t = tid - B * N;
        int b = t >> 13, col = t & 8191;
        const float* p = &g_colpart[((long)b * RTILES) * M + col];
        float m = p[0];
#pragma unroll 8
        for (int rt = 1; rt < RTILES; rt++) m = fminf(m, p[(long)rt * M]);
        v = sqrtf(m + EPS) * (1.0f / (B * M));
    }
    sred[threadIdx.x] = v;
    __syncthreads();
    for (int s = 128; s > 0; s >>= 1) {
        if (threadIdx.x < s) sred[threadIdx.x] += sred[threadIdx.x + s];
        __syncthreads();
    }
    if (threadIdx.x == 0) g_bsum[blockIdx.x] = sred[0];
}

// ---------------- finalize pass 2: single block, plain store ----------------
__global__ void finalize2_kernel(float* __restrict__ out) {
    __shared__ float sred[256];
    sred[threadIdx.x] = g_bsum[threadIdx.x];
    __syncthreads();
    for (int s = 128; s > 0; s >>= 1) {
        if (threadIdx.x < s) sred[threadIdx.x] += sred[threadIdx.x + s];
        __syncthreads();
    }
    if (threadIdx.x == 0) out[0] = sred[0];
}

extern "C" void kernel_launch(void* const* d_in, const int* in_sizes, int n_in,
                              void* d_out, int out_size) {
    const float* source  = (const float*)d_in[0];
    const float* target  = (const float*)d_in[1];
    const float* weights = (const float*)d_in[2];
    float* out = (float*)d_out;

    dim3 grid(CGROUPS, RTILES, B);
    tile_kernel<<<grid, 256>>>(source, target);

    finalize1_kernel<<<(B * N + B * M) / 256, 256>>>(weights);
    finalize2_kernel<<<1, 256>>>(out);
}